// round 13
// baseline (speedup 1.0000x reference)
#include <cuda_runtime.h>
#include <cuda_bf16.h>
#include <cstdint>
#include <cstddef>

// Problem constants
constexpr int BB  = 8;
constexpr int SS  = 4096;
constexpr int DD  = 1024;
constexpr int HH  = 16;
constexpr int DHH = 64;
constexpr int MTOK = BB * SS;          // 32768 tokens
constexpr int K3   = 3 * DD;           // 3072 packed-K (hi|lo|hi vs hi|hi|lo)
constexpr int D3   = 3 * DD;           // fused QKV output width

// ---------------------------------------------------------------------------
// Scratch (device globals: no allocation allowed anywhere)
// ---------------------------------------------------------------------------
__device__ float g_qkv[(size_t)MTOK * D3];             // [m][q|k|v] fp32
__device__ __nv_bfloat16 g_xs  [(size_t)MTOK * K3];    // x   split [hi|lo|hi]
__device__ __nv_bfloat16 g_cs  [(size_t)MTOK * K3];    // ctx split [hi|lo|hi]
__device__ __nv_bfloat16 g_wqkv[(size_t)D3 * K3];      // [wq;wk;wv] split [hi|hi|lo]
__device__ __nv_bfloat16 g_wos [(size_t)DD * K3];      // wo split   [hi|hi|lo]

// ---------------------------------------------------------------------------
// Helpers
// ---------------------------------------------------------------------------
__device__ __forceinline__ uint32_t smem_u32(const void* p) {
    uint32_t a;
    asm("{ .reg .u64 t; cvta.to.shared.u64 t, %1; cvt.u32.u64 %0, t; }"
        : "=r"(a) : "l"(p));
    return a;
}

__device__ __forceinline__ void cp16(uint32_t dst, const void* src) {
    asm volatile("cp.async.cg.shared.global [%0], [%1], 16;"
                 :: "r"(dst), "l"(src) : "memory");
}

__device__ __forceinline__ uint32_t swz(uint32_t off) {
    return off ^ ((off >> 3) & 0x70);   // SW128 within 1024B blocks
}

__device__ __forceinline__ void ldsm4(uint32_t r[4], uint32_t addr) {
    asm volatile("ldmatrix.sync.aligned.m8n8.x4.shared.b16 {%0,%1,%2,%3}, [%4];"
                 : "=r"(r[0]), "=r"(r[1]), "=r"(r[2]), "=r"(r[3]) : "r"(addr));
}

__device__ __forceinline__ void mma16816(float d[4], const uint32_t a[4],
                                         uint32_t b0, uint32_t b1) {
    asm volatile(
        "mma.sync.aligned.m16n8k16.row.col.f32.bf16.bf16.f32 "
        "{%0,%1,%2,%3}, {%4,%5,%6,%7}, {%8,%9}, {%0,%1,%2,%3};"
        : "+f"(d[0]), "+f"(d[1]), "+f"(d[2]), "+f"(d[3])
        : "r"(a[0]), "r"(a[1]), "r"(a[2]), "r"(a[3]), "r"(b0), "r"(b1));
}

// ---------------------------------------------------------------------------
// Split-precision conversion bodies
// act pattern [hi|lo|hi], wt pattern [hi|hi|lo]
// ---------------------------------------------------------------------------
struct alignas(16) B8 { __nv_bfloat16 v[8]; };

__device__ __forceinline__ void split_body(const float* __restrict__ src,
                                           __nv_bfloat16* __restrict__ dst,
                                           size_t idx, int act)
{
    const size_t row = idx >> 10;
    const int    col = (int)(idx & 1023);
    const float4 a = *(const float4*)(src + idx);
    const float4 b = *(const float4*)(src + idx + 4);
    float f[8] = {a.x, a.y, a.z, a.w, b.x, b.y, b.z, b.w};
    B8 ph, pl;
    #pragma unroll
    for (int i = 0; i < 8; i++) {
        __nv_bfloat16 h = __float2bfloat16(f[i]);
        ph.v[i] = h;
        pl.v[i] = __float2bfloat16(f[i] - __bfloat162float(h));
    }
    __nv_bfloat16* base = dst + row * K3 + col;
    *(B8*)(base)        = ph;
    *(B8*)(base + 1024) = act ? pl : ph;
    *(B8*)(base + 2048) = act ? ph : pl;
}

__global__ __launch_bounds__(256)
void split3(const float* __restrict__ src, __nv_bfloat16* __restrict__ dst, int act)
{
    const size_t idx = ((size_t)blockIdx.x * 256 + threadIdx.x) * 8;
    split_body(src, dst, idx, act);
}

// all 4 weight splits in one launch: grid 2048 (512 per weight)
__global__ __launch_bounds__(256)
void splitW(const float* __restrict__ wq, const float* __restrict__ wk,
            const float* __restrict__ wv, const float* __restrict__ wo,
            __nv_bfloat16* __restrict__ wqkv, __nv_bfloat16* __restrict__ wos)
{
    const int sel = blockIdx.x >> 9;
    const float* src = (sel == 0) ? wq : (sel == 1) ? wk : (sel == 2) ? wv : wo;
    __nv_bfloat16* dst =
        (sel == 0) ? wqkv :
        (sel == 1) ? wqkv + (size_t)DD * K3 :
        (sel == 2) ? wqkv + (size_t)2 * DD * K3 : wos;
    const size_t idx = ((size_t)(blockIdx.x & 511) * 256 + threadIdx.x) * 8;
    split_body(src, dst, idx, 0);
}

// ---------------------------------------------------------------------------
// bf16 mma.sync GEMM (NT): C[m][n] = sum_k A[m][k]*B[n][k] + bias[n]
// Tile 128x256, BK=64 (SW128), 8 warps (2x4) of 64x64, 4-stage cp.async
// pipeline (2-chunk prefetch distance). Mainloop identical to validated R11.
// Bias selected per 1024-column group (fused QKV); C row stride ldc.
// ---------------------------------------------------------------------------
constexpr int GBM = 128, GBN = 256, GBK = 64;
constexpr int STAGES = 4;
constexpr int NCH = K3 / GBK;                 // 48
constexpr int ASZ = GBM * 128;                // 16384 B / stage
constexpr int BSZ = GBN * 128;                // 32768 B / stage
constexpr int STG = ASZ + BSZ;                // 49152
constexpr int GEMM_SMEM = STAGES * STG;       // 196608

__global__ __launch_bounds__(256, 1)
void gemm_mma(const __nv_bfloat16* __restrict__ A,
              const __nv_bfloat16* __restrict__ B,
              const float* __restrict__ b0p,
              const float* __restrict__ b1p,
              const float* __restrict__ b2p,
              float* __restrict__ C, int ldc)
{
    extern __shared__ char smem[];
    const uint32_t sb = smem_u32(smem);
    const int tid  = threadIdx.x;
    const int wid  = tid >> 5;
    const int lane = tid & 31;
    const int m0 = blockIdx.y * GBM;
    const int n0 = blockIdx.x * GBN;
    const int wm = (wid >> 2) * 64;           // warp m offset in tile
    const int wn = (wid & 3) * 64;            // warp n offset in tile

    float acc[4][8][4];
    #pragma unroll
    for (int i = 0; i < 4; i++)
        #pragma unroll
        for (int j = 0; j < 8; j++)
            #pragma unroll
            for (int c = 0; c < 4; c++) acc[i][j][c] = 0.0f;

    auto load_stage = [&](int i, int s) {
        const int k0 = i * GBK;
        const uint32_t ab = sb + s * STG;
        const uint32_t bb = ab + ASZ;
        #pragma unroll
        for (int j = 0; j < 12; j++) {
            const int c  = tid + j * 256;
            const int cc = c & 7;
            if (c < 1024) {
                const int r = c >> 3;          // A rows 0..127
                cp16(ab + swz((uint32_t)(r * 128 + cc * 16)),
                     A + (size_t)(m0 + r) * K3 + k0 + cc * 8);
            } else {
                const int r = (c - 1024) >> 3; // B rows 0..255
                cp16(bb + swz((uint32_t)(r * 128 + cc * 16)),
                     B + (size_t)(n0 + r) * K3 + k0 + cc * 8);
            }
        }
        asm volatile("cp.async.commit_group;" ::: "memory");
    };

    // 3-deep prologue -> 2-chunk prefetch distance in steady state
    load_stage(0, 0);
    load_stage(1, 1);
    load_stage(2, 2);

    // ldmatrix per-lane source rows (validated fragment mapping)
    const int arow = wm + (lane & 15);
    const int akb  = (lane >> 4) * 16;
    const int brow = wn + (lane & 7) + ((lane >> 4) << 3);
    const int bkb  = ((lane >> 3) & 1) * 16;

    #pragma unroll 4
    for (int i = 0; i < NCH; i++) {
        asm volatile("cp.async.wait_group 2;" ::: "memory");
        __syncthreads();
        const int s = i % STAGES;
        const uint32_t ab = sb + s * STG;
        const uint32_t bb = ab + ASZ;

        #pragma unroll
        for (int kk = 0; kk < 4; kk++) {
            const int c0 = kk * 32;
            uint32_t af[4][4], bf[4][4];
            #pragma unroll
            for (int mi = 0; mi < 4; mi++)
                ldsm4(af[mi], ab + swz((uint32_t)((arow + mi * 16) * 128 + c0 + akb)));
            #pragma unroll
            for (int nj = 0; nj < 4; nj++)
                ldsm4(bf[nj], bb + swz((uint32_t)((brow + nj * 16) * 128 + c0 + bkb)));
            #pragma unroll
            for (int mi = 0; mi < 4; mi++)
                #pragma unroll
                for (int nj = 0; nj < 4; nj++) {
                    mma16816(acc[mi][2 * nj],     af[mi], bf[nj][0], bf[nj][1]);
                    mma16816(acc[mi][2 * nj + 1], af[mi], bf[nj][2], bf[nj][3]);
                }
        }
        if (i + 3 < NCH) load_stage(i + 3, (i + 3) % STAGES);
    }

    // Epilogue: bias per 1024-column group (fused QKV), float2 stores
    const int sel = n0 >> 10;
    const float* bias = (sel == 0) ? b0p : (sel == 1) ? b1p : b2p;
    const int rbase = m0 + wm + (lane >> 2);
    const int cbase = n0 + wn + 2 * (lane & 3);          // C column
    const int bbase = (n0 & 1023) + wn + 2 * (lane & 3); // bias column
    float2 bb2[8];
    #pragma unroll
    for (int nj = 0; nj < 8; nj++) {
        bb2[nj].x = bias[bbase + nj * 8];
        bb2[nj].y = bias[bbase + nj * 8 + 1];
    }
    #pragma unroll
    for (int mi = 0; mi < 4; mi++) {
        #pragma unroll
        for (int nj = 0; nj < 8; nj++) {
            const int cc = cbase + nj * 8;
            float2 v0 = { acc[mi][nj][0] + bb2[nj].x, acc[mi][nj][1] + bb2[nj].y };
            float2 v1 = { acc[mi][nj][2] + bb2[nj].x, acc[mi][nj][3] + bb2[nj].y };
            *(float2*)(C + (size_t)(rbase + mi * 16)     * ldc + cc) = v0;
            *(float2*)(C + (size_t)(rbase + mi * 16 + 8) * ldc + cc) = v1;
        }
    }
}

// ---------------------------------------------------------------------------
// Per-token attention over the HEAD axis + fused split-bf16 ctx emission.
// Reads qkv row [q|k|v] (3*1024 fp32), writes g_cs [hi|lo|hi] directly.
// Scores: d-outer loop, per-lane fixed g = lane&15 -> k broadcast-friendly.
// Ctx: lane-owned v columns register-cached; sp reads are warp broadcasts.
// ---------------------------------------------------------------------------
constexpr int WPB = 2;
constexpr int RPAD = 66;   // even -> float2 reads stay 8B-aligned, conflict-free

__global__ __launch_bounds__(WPB * 32)
void attn_kernel(const float* __restrict__ qkv, __nv_bfloat16* __restrict__ cs)
{
    __shared__ float sq[WPB][HH * RPAD];
    __shared__ float sk[WPB][HH * RPAD];
    __shared__ float sv[WPB][HH * RPAD];
    __shared__ float sp[WPB][HH][17];

    const int w    = threadIdx.x >> 5;
    const int lane = threadIdx.x & 31;
    const size_t token = (size_t)blockIdx.x * WPB + w;

    const float* qt = qkv + token * D3;
    const float* kt = qt + DD;
    const float* vt = qt + 2 * DD;

    #pragma unroll
    for (int i = 0; i < 8; i++) {
        const int e   = i * 128 + lane * 4;
        const int row = e >> 6;
        const int col = e & 63;
        const float4 qv = *(const float4*)(qt + e);
        const float4 kv = *(const float4*)(kt + e);
        const float4 vv = *(const float4*)(vt + e);
        float* sqr = &sq[w][row * RPAD + col];
        float* skr = &sk[w][row * RPAD + col];
        float* svr = &sv[w][row * RPAD + col];
        sqr[0] = qv.x; sqr[1] = qv.y; sqr[2] = qv.z; sqr[3] = qv.w;
        skr[0] = kv.x; skr[1] = kv.y; skr[2] = kv.z; skr[3] = kv.w;
        svr[0] = vv.x; svr[1] = vv.y; svr[2] = vv.z; svr[3] = vv.w;
    }
    __syncwarp();

    // Scores. Lane computes 8 (h,g) pairs with g = lane&15 fixed,
    // h = 2i + (lane>>4). d-outer: 1 k read + 8 q broadcast reads per d.
    {
        const int g  = lane & 15;
        const int lh = lane >> 4;
        const float* kr = &sk[w][g * RPAD];
        float accv[8];
        #pragma unroll
        for (int i = 0; i < 8; i++) accv[i] = 0.0f;
        #pragma unroll
        for (int d = 0; d < DHH; d++) {
            const float kd = kr[d];
            #pragma unroll
            for (int i = 0; i < 8; i++)
                accv[i] = fmaf(sq[w][(2 * i + lh) * RPAD + d], kd, accv[i]);
        }
        #pragma unroll
        for (int i = 0; i < 8; i++)
            sp[w][2 * i + lh][g] = accv[i] * 0.125f;
    }
    __syncwarp();

    if (lane < HH) {
        float mx = -1e30f;
        #pragma unroll
        for (int g = 0; g < HH; g++) mx = fmaxf(mx, sp[w][lane][g]);
        float e[HH];
        float s = 0.0f;
        #pragma unroll
        for (int g = 0; g < HH; g++) { e[g] = __expf(sp[w][lane][g] - mx); s += e[g]; }
        const float inv = 1.0f / s;
        #pragma unroll
        for (int g = 0; g < HH; g++) sp[w][lane][g] = e[g] * inv;
    }
    __syncwarp();

    // Ctx: register-cache the lane's two v columns (d = 2*lane, 2*lane+1)
    float vr0[HH], vr1[HH];
    #pragma unroll
    for (int g = 0; g < HH; g++) {
        const float2 vv = *(const float2*)&sv[w][g * RPAD + 2 * lane];
        vr0[g] = vv.x; vr1[g] = vv.y;
    }
    __nv_bfloat16* crow = cs + token * K3;
    #pragma unroll
    for (int h = 0; h < HH; h++) {
        float a0 = 0.0f, a1 = 0.0f;
        #pragma unroll
        for (int g = 0; g < HH; g++) {
            const float p = sp[w][h][g];   // warp-wide broadcast read
            a0 = fmaf(p, vr0[g], a0);
            a1 = fmaf(p, vr1[g], a1);
        }
        const __nv_bfloat16 h0 = __float2bfloat16(a0);
        const __nv_bfloat16 h1 = __float2bfloat16(a1);
        const __nv_bfloat16 l0 = __float2bfloat16(a0 - __bfloat162float(h0));
        const __nv_bfloat16 l1 = __float2bfloat16(a1 - __bfloat162float(h1));
        __nv_bfloat162 hp, lp;
        hp.x = h0; hp.y = h1;
        lp.x = l0; lp.y = l1;
        const int col = h * DHH + 2 * lane;
        *(__nv_bfloat162*)(crow + col)        = hp;   // hi
        *(__nv_bfloat162*)(crow + col + 1024) = lp;   // lo
        *(__nv_bfloat162*)(crow + col + 2048) = hp;   // hi
    }
}

// ---------------------------------------------------------------------------
// Launch
// ---------------------------------------------------------------------------
extern "C" void kernel_launch(void* const* d_in, const int* in_sizes, int n_in,
                              void* d_out, int out_size)
{
    const float* x  = (const float*)d_in[0];
    const float* wq = (const float*)d_in[1];
    const float* bq = (const float*)d_in[2];
    const float* wk = (const float*)d_in[3];
    const float* bk = (const float*)d_in[4];
    const float* wv = (const float*)d_in[5];
    const float* bv = (const float*)d_in[6];
    const float* wo = (const float*)d_in[7];
    const float* bo = (const float*)d_in[8];
    float* out = (float*)d_out;

    float *qkv;
    __nv_bfloat16 *xs, *cs, *wqkv, *wos;
    cudaGetSymbolAddress((void**)&qkv,  g_qkv);
    cudaGetSymbolAddress((void**)&xs,   g_xs);
    cudaGetSymbolAddress((void**)&cs,   g_cs);
    cudaGetSymbolAddress((void**)&wqkv, g_wqkv);
    cudaGetSymbolAddress((void**)&wos,  g_wos);

    cudaFuncSetAttribute(gemm_mma,
                         cudaFuncAttributeMaxDynamicSharedMemorySize, GEMM_SMEM);

    const int act_blocks = (int)(((size_t)MTOK * DD / 8) / 256);   // 16384

    split3<<<act_blocks, 256>>>(x, xs, 1);
    splitW<<<2048, 256>>>(wq, wk, wv, wo, wqkv, wos);

    // Fused QKV GEMM: N = 3072
    dim3 gq(D3 / GBN, MTOK / GBM);   // (12, 256)
    gemm_mma<<<gq, 256, GEMM_SMEM>>>(xs, wqkv, bq, bk, bv, qkv, D3);

    attn_kernel<<<MTOK / WPB, WPB * 32>>>(qkv, cs);

    // Output GEMM: N = 1024
    dim3 go(DD / GBN, MTOK / GBM);   // (4, 256)
    gemm_mma<<<go, 256, GEMM_SMEM>>>(cs, wos, bo, bo, bo, out, DD);
}

// round 14
// speedup vs baseline: 1.0030x; 1.0030x over previous
#include <cuda_runtime.h>
#include <cuda_bf16.h>
#include <cstdint>
#include <cstddef>

// Problem constants
constexpr int BB  = 8;
constexpr int SS  = 4096;
constexpr int DD  = 1024;
constexpr int HH  = 16;
constexpr int DHH = 64;
constexpr int MTOK = BB * SS;          // 32768 tokens
constexpr int K3   = 3 * DD;           // 3072 packed-K (hi|lo|hi vs hi|hi|lo)
constexpr int D3   = 3 * DD;           // fused QKV output width

// ---------------------------------------------------------------------------
// Scratch (device globals: no allocation allowed anywhere)
// ---------------------------------------------------------------------------
__device__ float g_qkv[(size_t)MTOK * D3];             // [m][q|k|v] fp32
__device__ __nv_bfloat16 g_xs  [(size_t)MTOK * K3];    // x   split [hi|lo|hi]
__device__ __nv_bfloat16 g_cs  [(size_t)MTOK * K3];    // ctx split [hi|lo|hi]
__device__ __nv_bfloat16 g_wqkv[(size_t)D3 * K3];      // [wq;wk;wv] split [hi|hi|lo]
__device__ __nv_bfloat16 g_wos [(size_t)DD * K3];      // wo split   [hi|hi|lo]

// ---------------------------------------------------------------------------
// Helpers
// ---------------------------------------------------------------------------
__device__ __forceinline__ uint32_t smem_u32(const void* p) {
    uint32_t a;
    asm("{ .reg .u64 t; cvta.to.shared.u64 t, %1; cvt.u32.u64 %0, t; }"
        : "=r"(a) : "l"(p));
    return a;
}

__device__ __forceinline__ void cp16(uint32_t dst, const void* src) {
    asm volatile("cp.async.cg.shared.global [%0], [%1], 16;"
                 :: "r"(dst), "l"(src) : "memory");
}

__device__ __forceinline__ uint32_t swz(uint32_t off) {
    return off ^ ((off >> 3) & 0x70);   // SW128 within 1024B blocks
}

__device__ __forceinline__ void ldsm4(uint32_t r[4], uint32_t addr) {
    asm volatile("ldmatrix.sync.aligned.m8n8.x4.shared.b16 {%0,%1,%2,%3}, [%4];"
                 : "=r"(r[0]), "=r"(r[1]), "=r"(r[2]), "=r"(r[3]) : "r"(addr));
}

__device__ __forceinline__ void mma16816(float d[4], const uint32_t a[4],
                                         uint32_t b0, uint32_t b1) {
    asm volatile(
        "mma.sync.aligned.m16n8k16.row.col.f32.bf16.bf16.f32 "
        "{%0,%1,%2,%3}, {%4,%5,%6,%7}, {%8,%9}, {%0,%1,%2,%3};"
        : "+f"(d[0]), "+f"(d[1]), "+f"(d[2]), "+f"(d[3])
        : "r"(a[0]), "r"(a[1]), "r"(a[2]), "r"(a[3]), "r"(b0), "r"(b1));
}

// ---------------------------------------------------------------------------
// Split-precision conversion body
// act pattern [hi|lo|hi], wt pattern [hi|hi|lo]
// ---------------------------------------------------------------------------
struct alignas(16) B8 { __nv_bfloat16 v[8]; };

__device__ __forceinline__ void split_body(const float* __restrict__ src,
                                           __nv_bfloat16* __restrict__ dst,
                                           size_t idx, int act)
{
    const size_t row = idx >> 10;
    const int    col = (int)(idx & 1023);
    const float4 a = *(const float4*)(src + idx);
    const float4 b = *(const float4*)(src + idx + 4);
    float f[8] = {a.x, a.y, a.z, a.w, b.x, b.y, b.z, b.w};
    B8 ph, pl;
    #pragma unroll
    for (int i = 0; i < 8; i++) {
        __nv_bfloat16 h = __float2bfloat16(f[i]);
        ph.v[i] = h;
        pl.v[i] = __float2bfloat16(f[i] - __bfloat162float(h));
    }
    __nv_bfloat16* base = dst + row * K3 + col;
    *(B8*)(base)        = ph;
    *(B8*)(base + 1024) = act ? pl : ph;
    *(B8*)(base + 2048) = act ? ph : pl;
}

// One launch: activation split (blocks 0..16383) + 4 weight splits (16384..18431)
constexpr int ACT_BLOCKS = (int)(((size_t)MTOK * DD / 8) / 256);  // 16384
constexpr int WT_BLOCKS  = (int)(((size_t)DD * DD / 8) / 256);    // 512

__global__ __launch_bounds__(256)
void split_all(const float* __restrict__ x,
               const float* __restrict__ wq, const float* __restrict__ wk,
               const float* __restrict__ wv, const float* __restrict__ wo,
               __nv_bfloat16* __restrict__ xs,
               __nv_bfloat16* __restrict__ wqkv,
               __nv_bfloat16* __restrict__ wos)
{
    const int b = blockIdx.x;
    if (b < ACT_BLOCKS) {
        const size_t idx = ((size_t)b * 256 + threadIdx.x) * 8;
        split_body(x, xs, idx, 1);
    } else {
        const int wb  = b - ACT_BLOCKS;
        const int sel = wb >> 9;                 // 0..3
        const float* src = (sel == 0) ? wq : (sel == 1) ? wk : (sel == 2) ? wv : wo;
        __nv_bfloat16* dst =
            (sel == 0) ? wqkv :
            (sel == 1) ? wqkv + (size_t)DD * K3 :
            (sel == 2) ? wqkv + (size_t)2 * DD * K3 : wos;
        const size_t idx = ((size_t)(wb & 511) * 256 + threadIdx.x) * 8;
        split_body(src, dst, idx, 0);
    }
}

// ---------------------------------------------------------------------------
// bf16 mma.sync GEMM (NT): C[m][n] = sum_k A[m][k]*B[n][k] + bias[n]
// Tile 128x256, BK=64 (SW128), 8 warps (2x4) of 64x64, 4-stage cp.async
// pipeline (2-chunk prefetch distance). Mainloop identical to validated R11.
// Bias selected per 1024-column group (fused QKV); C row stride ldc.
// ---------------------------------------------------------------------------
constexpr int GBM = 128, GBN = 256, GBK = 64;
constexpr int STAGES = 4;
constexpr int NCH = K3 / GBK;                 // 48
constexpr int ASZ = GBM * 128;                // 16384 B / stage
constexpr int BSZ = GBN * 128;                // 32768 B / stage
constexpr int STG = ASZ + BSZ;                // 49152
constexpr int GEMM_SMEM = STAGES * STG;       // 196608

__global__ __launch_bounds__(256, 1)
void gemm_mma(const __nv_bfloat16* __restrict__ A,
              const __nv_bfloat16* __restrict__ B,
              const float* __restrict__ b0p,
              const float* __restrict__ b1p,
              const float* __restrict__ b2p,
              float* __restrict__ C, int ldc)
{
    extern __shared__ char smem[];
    const uint32_t sb = smem_u32(smem);
    const int tid  = threadIdx.x;
    const int wid  = tid >> 5;
    const int lane = tid & 31;
    const int m0 = blockIdx.y * GBM;
    const int n0 = blockIdx.x * GBN;
    const int wm = (wid >> 2) * 64;           // warp m offset in tile
    const int wn = (wid & 3) * 64;            // warp n offset in tile

    float acc[4][8][4];
    #pragma unroll
    for (int i = 0; i < 4; i++)
        #pragma unroll
        for (int j = 0; j < 8; j++)
            #pragma unroll
            for (int c = 0; c < 4; c++) acc[i][j][c] = 0.0f;

    auto load_stage = [&](int i, int s) {
        const int k0 = i * GBK;
        const uint32_t ab = sb + s * STG;
        const uint32_t bb = ab + ASZ;
        #pragma unroll
        for (int j = 0; j < 12; j++) {
            const int c  = tid + j * 256;
            const int cc = c & 7;
            if (c < 1024) {
                const int r = c >> 3;          // A rows 0..127
                cp16(ab + swz((uint32_t)(r * 128 + cc * 16)),
                     A + (size_t)(m0 + r) * K3 + k0 + cc * 8);
            } else {
                const int r = (c - 1024) >> 3; // B rows 0..255
                cp16(bb + swz((uint32_t)(r * 128 + cc * 16)),
                     B + (size_t)(n0 + r) * K3 + k0 + cc * 8);
            }
        }
        asm volatile("cp.async.commit_group;" ::: "memory");
    };

    // 3-deep prologue -> 2-chunk prefetch distance in steady state
    load_stage(0, 0);
    load_stage(1, 1);
    load_stage(2, 2);

    // ldmatrix per-lane source rows (validated fragment mapping)
    const int arow = wm + (lane & 15);
    const int akb  = (lane >> 4) * 16;
    const int brow = wn + (lane & 7) + ((lane >> 4) << 3);
    const int bkb  = ((lane >> 3) & 1) * 16;

    #pragma unroll 4
    for (int i = 0; i < NCH; i++) {
        asm volatile("cp.async.wait_group 2;" ::: "memory");
        __syncthreads();
        const int s = i % STAGES;
        const uint32_t ab = sb + s * STG;
        const uint32_t bb = ab + ASZ;

        #pragma unroll
        for (int kk = 0; kk < 4; kk++) {
            const int c0 = kk * 32;
            uint32_t af[4][4], bf[4][4];
            #pragma unroll
            for (int mi = 0; mi < 4; mi++)
                ldsm4(af[mi], ab + swz((uint32_t)((arow + mi * 16) * 128 + c0 + akb)));
            #pragma unroll
            for (int nj = 0; nj < 4; nj++)
                ldsm4(bf[nj], bb + swz((uint32_t)((brow + nj * 16) * 128 + c0 + bkb)));
            #pragma unroll
            for (int mi = 0; mi < 4; mi++)
                #pragma unroll
                for (int nj = 0; nj < 4; nj++) {
                    mma16816(acc[mi][2 * nj],     af[mi], bf[nj][0], bf[nj][1]);
                    mma16816(acc[mi][2 * nj + 1], af[mi], bf[nj][2], bf[nj][3]);
                }
        }
        if (i + 3 < NCH) load_stage(i + 3, (i + 3) % STAGES);
    }

    // Epilogue: bias per 1024-column group (fused QKV), float2 stores
    const int sel = n0 >> 10;
    const float* bias = (sel == 0) ? b0p : (sel == 1) ? b1p : b2p;
    const int rbase = m0 + wm + (lane >> 2);
    const int cbase = n0 + wn + 2 * (lane & 3);          // C column
    const int bbase = (n0 & 1023) + wn + 2 * (lane & 3); // bias column
    float2 bb2[8];
    #pragma unroll
    for (int nj = 0; nj < 8; nj++) {
        bb2[nj].x = bias[bbase + nj * 8];
        bb2[nj].y = bias[bbase + nj * 8 + 1];
    }
    #pragma unroll
    for (int mi = 0; mi < 4; mi++) {
        #pragma unroll
        for (int nj = 0; nj < 8; nj++) {
            const int cc = cbase + nj * 8;
            float2 v0 = { acc[mi][nj][0] + bb2[nj].x, acc[mi][nj][1] + bb2[nj].y };
            float2 v1 = { acc[mi][nj][2] + bb2[nj].x, acc[mi][nj][3] + bb2[nj].y };
            *(float2*)(C + (size_t)(rbase + mi * 16)     * ldc + cc) = v0;
            *(float2*)(C + (size_t)(rbase + mi * 16 + 8) * ldc + cc) = v1;
        }
    }
}

// ---------------------------------------------------------------------------
// Per-token attention over the HEAD axis + fused split-bf16 ctx emission.
// Scores: lane's k-row register-cached as 16x float4; q reads are 2-way
// broadcast LDS.128. Ctx: lane-owned v columns register-cached.
// RPAD = 68 (multiple of 4) keeps all float4 row accesses 16B-aligned.
// ---------------------------------------------------------------------------
constexpr int WPB = 2;
constexpr int RPAD = 68;

__global__ __launch_bounds__(WPB * 32)
void attn_kernel(const float* __restrict__ qkv, __nv_bfloat16* __restrict__ cs)
{
    __shared__ float sq[WPB][HH * RPAD];
    __shared__ float sk[WPB][HH * RPAD];
    __shared__ float sv[WPB][HH * RPAD];
    __shared__ float sp[WPB][HH][17];

    const int w    = threadIdx.x >> 5;
    const int lane = threadIdx.x & 31;
    const size_t token = (size_t)blockIdx.x * WPB + w;

    const float* qt = qkv + token * D3;
    const float* kt = qt + DD;
    const float* vt = qt + 2 * DD;

    #pragma unroll
    for (int i = 0; i < 8; i++) {
        const int e   = i * 128 + lane * 4;
        const int row = e >> 6;
        const int col = e & 63;
        const float4 qv = *(const float4*)(qt + e);
        const float4 kv = *(const float4*)(kt + e);
        const float4 vv = *(const float4*)(vt + e);
        *(float4*)&sq[w][row * RPAD + col] = qv;
        *(float4*)&sk[w][row * RPAD + col] = kv;
        *(float4*)&sv[w][row * RPAD + col] = vv;
    }
    __syncwarp();

    // Scores: lane owns k-row g = lane&15 (register-cached), computes 8 h values
    // h = 2i + (lane>>4). q reads are 2-way broadcasts.
    {
        const int g  = lane & 15;
        const int lh = lane >> 4;
        float4 kreg[16];
        #pragma unroll
        for (int j = 0; j < 16; j++)
            kreg[j] = *(const float4*)&sk[w][g * RPAD + 4 * j];
        float accv[8];
        #pragma unroll
        for (int i = 0; i < 8; i++) accv[i] = 0.0f;
        #pragma unroll
        for (int j = 0; j < 16; j++) {
            #pragma unroll
            for (int i = 0; i < 8; i++) {
                const float4 q4 = *(const float4*)&sq[w][(2 * i + lh) * RPAD + 4 * j];
                float t = q4.x * kreg[j].x;
                t = fmaf(q4.y, kreg[j].y, t);
                t = fmaf(q4.z, kreg[j].z, t);
                t = fmaf(q4.w, kreg[j].w, t);
                accv[i] += t;
            }
        }
        #pragma unroll
        for (int i = 0; i < 8; i++)
            sp[w][2 * i + lh][g] = accv[i] * 0.125f;
    }
    __syncwarp();

    if (lane < HH) {
        float mx = -1e30f;
        #pragma unroll
        for (int g = 0; g < HH; g++) mx = fmaxf(mx, sp[w][lane][g]);
        float e[HH];
        float s = 0.0f;
        #pragma unroll
        for (int g = 0; g < HH; g++) { e[g] = __expf(sp[w][lane][g] - mx); s += e[g]; }
        const float inv = 1.0f / s;
        #pragma unroll
        for (int g = 0; g < HH; g++) sp[w][lane][g] = e[g] * inv;
    }
    __syncwarp();

    // Ctx: register-cache the lane's two v columns (d = 2*lane, 2*lane+1)
    float vr0[HH], vr1[HH];
    #pragma unroll
    for (int g = 0; g < HH; g++) {
        const float2 vv = *(const float2*)&sv[w][g * RPAD + 2 * lane];
        vr0[g] = vv.x; vr1[g] = vv.y;
    }
    __nv_bfloat16* crow = cs + token * K3;
    #pragma unroll
    for (int h = 0; h < HH; h++) {
        float a0 = 0.0f, a1 = 0.0f;
        #pragma unroll
        for (int g = 0; g < HH; g++) {
            const float p = sp[w][h][g];   // warp-wide broadcast read
            a0 = fmaf(p, vr0[g], a0);
            a1 = fmaf(p, vr1[g], a1);
        }
        const __nv_bfloat16 h0 = __float2bfloat16(a0);
        const __nv_bfloat16 h1 = __float2bfloat16(a1);
        const __nv_bfloat16 l0 = __float2bfloat16(a0 - __bfloat162float(h0));
        const __nv_bfloat16 l1 = __float2bfloat16(a1 - __bfloat162float(h1));
        __nv_bfloat162 hp, lp;
        hp.x = h0; hp.y = h1;
        lp.x = l0; lp.y = l1;
        const int col = h * DHH + 2 * lane;
        *(__nv_bfloat162*)(crow + col)        = hp;   // hi
        *(__nv_bfloat162*)(crow + col + 1024) = lp;   // lo
        *(__nv_bfloat162*)(crow + col + 2048) = hp;   // hi
    }
}

// ---------------------------------------------------------------------------
// Launch
// ---------------------------------------------------------------------------
extern "C" void kernel_launch(void* const* d_in, const int* in_sizes, int n_in,
                              void* d_out, int out_size)
{
    const float* x  = (const float*)d_in[0];
    const float* wq = (const float*)d_in[1];
    const float* bq = (const float*)d_in[2];
    const float* wk = (const float*)d_in[3];
    const float* bk = (const float*)d_in[4];
    const float* wv = (const float*)d_in[5];
    const float* bv = (const float*)d_in[6];
    const float* wo = (const float*)d_in[7];
    const float* bo = (const float*)d_in[8];
    float* out = (float*)d_out;

    float *qkv;
    __nv_bfloat16 *xs, *cs, *wqkv, *wos;
    cudaGetSymbolAddress((void**)&qkv,  g_qkv);
    cudaGetSymbolAddress((void**)&xs,   g_xs);
    cudaGetSymbolAddress((void**)&cs,   g_cs);
    cudaGetSymbolAddress((void**)&wqkv, g_wqkv);
    cudaGetSymbolAddress((void**)&wos,  g_wos);

    cudaFuncSetAttribute(gemm_mma,
                         cudaFuncAttributeMaxDynamicSharedMemorySize, GEMM_SMEM);

    // All splits in one launch
    split_all<<<ACT_BLOCKS + 4 * WT_BLOCKS, 256>>>(x, wq, wk, wv, wo, xs, wqkv, wos);

    // Fused QKV GEMM: N = 3072
    dim3 gq(D3 / GBN, MTOK / GBM);   // (12, 256)
    gemm_mma<<<gq, 256, GEMM_SMEM>>>(xs, wqkv, bq, bk, bv, qkv, D3);

    attn_kernel<<<MTOK / WPB, WPB * 32>>>(qkv, cs);

    // Output GEMM: N = 1024
    dim3 go(DD / GBN, MTOK / GBM);   // (4, 256)
    gemm_mma<<<go, 256, GEMM_SMEM>>>(cs, wos, bo, bo, bo, out, DD);
}